// round 13
// baseline (speedup 1.0000x reference)
#include <cuda_runtime.h>
#include <stdint.h>

#define NUM_BINS 256
#define NCH_SAMPLE 3
#define NCH_TOTAL 6
#define NPX (2048 * 4096)

#define SLICES 197                 // slices per channel
#define NCTAS (SLICES * 3)         // 591 CTAs total (<= 148 SMs * 4 resident)
#define GPC 10646                  // float4 groups per CTA: ceil(2097152/197)
#define TPB 512                    // threads per CTA (4*512 = 2048/SM = 100% occ)
#define NREP 8                     // smem histogram replicas
#define BIN_SMEM (GPC * 4)         // 42584 B dynamic smem for packed bins

// Static device scratch (zeroed at load; last-done CTA restores zeros each
// run, so graph replays are deterministic).
__device__ int g_hist[NCH_SAMPLE][NUM_BINS];
__device__ int g_ticket;
__device__ int g_done;

// Single persistent kernel (R10 structure, 512-thread CTAs for occupancy):
//  A: hist + binize own sample slice (bins kept in dynamic smem)
//  B: grid-stride copy of target channels (hides the hist sync)
//  C: spin on ticket, build own channel's LUT (t<256 active)
//  D: apply LUT from smem bins -> output
__global__ void __launch_bounds__(TPB, 4)
equalize_fused_kernel(const float* __restrict__ img,
                      float* __restrict__ out, int npx) {
    const int t = threadIdx.x;
    const int c  = blockIdx.x % NCH_SAMPLE;     // channel
    const int sl = blockIdx.x / NCH_SAMPLE;     // slice within channel
    const int n4 = npx >> 2;
    const int base = sl * GPC;
    const int end  = min(base + GPC, n4);

    extern __shared__ uint32_t s_bins[];        // GPC packed bins (dynamic)
    __shared__ int   s_hist[NREP][NUM_BINS];    // 8 KB replicas / scan scratch
    __shared__ float s_lut[NUM_BINS];           // 1 KB
    __shared__ int   s_lastnz;

    // ---- Phase A: hist + binize (sample read happens exactly once) ----
    for (int i = t; i < NREP * NUM_BINS; i += TPB) ((int*)s_hist)[i] = 0;
    __syncthreads();

    {
        const float4* p = (const float4*)(img + (size_t)c * npx);
        const int sub = t & (NREP - 1);
        for (int g = base + t; g < end; g += TPB) {
            float4 v = __ldcs(&p[g]);
            int b0 = min(255, max(0, (int)v.x));
            int b1 = min(255, max(0, (int)v.y));
            int b2 = min(255, max(0, (int)v.z));
            int b3 = min(255, max(0, (int)v.w));
            s_bins[g - base] = (uint32_t)b0 | ((uint32_t)b1 << 8) |
                               ((uint32_t)b2 << 16) | ((uint32_t)b3 << 24);
            atomicAdd(&s_hist[sub][b0], 1);
            atomicAdd(&s_hist[sub][b1], 1);
            atomicAdd(&s_hist[sub][b2], 1);
            atomicAdd(&s_hist[sub][b3], 1);
        }
    }
    __syncthreads();
    if (t < NUM_BINS) {
        int s = 0;
        #pragma unroll
        for (int r = 0; r < NREP; r++) s += s_hist[r][t];
        if (s) atomicAdd(&g_hist[c][t], s);
    }
    __threadfence();                            // release hist before arrive
    if (t == 0) atomicAdd(&g_ticket, 1);

    // ---- Phase B: target copy (overlaps / hides the hist sync) ----
    {
        const float4* p = (const float4*)(img + (size_t)NCH_SAMPLE * npx);
        float4*       q = (float4*)(out + (size_t)NCH_SAMPLE * npx);
        const int tn4 = NCH_SAMPLE * n4;
        const int stride = NCTAS * TPB;
        int i = blockIdx.x * TPB + t;
        for (; i + stride < tn4; i += 2 * stride) {
            float4 a = __ldcs(&p[i]);
            float4 d = __ldcs(&p[i + stride]);
            __stcs(&q[i], a);
            __stcs(&q[i + stride], d);
        }
        if (i < tn4) __stcs(&q[i], __ldcs(&p[i]));
    }

    // ---- Phase C: wait for all hist arrivals, then build this channel's LUT
    if (t == 0) {
        while (*(volatile int*)&g_ticket != NCTAS) __nanosleep(128);
    }
    __syncthreads();
    __threadfence();

    {
        int* hist = s_hist[0];
        int* cum  = s_hist[1];
        int h = 0;
        if (t < NUM_BINS) {
            h = __ldcg(&g_hist[c][t]);
            hist[t] = h;
            cum[t]  = h;
        }
        if (t == 0) s_lastnz = 0;
        __syncthreads();

        #pragma unroll
        for (int off = 1; off < NUM_BINS; off <<= 1) {
            int tmp = 0;
            if (t < NUM_BINS && t >= off) tmp = cum[t - off];
            __syncthreads();
            if (t < NUM_BINS) cum[t] += tmp;
            __syncthreads();
        }
        if (t < NUM_BINS && h > 0) atomicMax(&s_lastnz, t);
        __syncthreads();

        if (t < NUM_BINS) {
            const int total = cum[NUM_BINS - 1];
            const int step  = (total - hist[s_lastnz]) / (NUM_BINS - 1);

            float outv;
            if (step == 0) {
                outv = (float)t;                // identity when step==0
            } else {
                int l = (t == 0) ? 0 : (cum[t - 1] + (step >> 1)) / step;
                outv = (float)min(NUM_BINS - 1, max(0, l));
            }
            s_lut[t] = outv;
        }
        __syncthreads();
    }

    // ---- Phase D: apply from smem bins (no global re-read of samples) ----
    {
        float4* q = (float4*)(out + (size_t)c * npx);
        for (int g = base + t; g < end; g += TPB) {
            uint32_t w = s_bins[g - base];
            float4 r;
            r.x = s_lut[w & 255];
            r.y = s_lut[(w >> 8) & 255];
            r.z = s_lut[(w >> 16) & 255];
            r.w = s_lut[w >> 24];
            __stcs(&q[g], r);
        }
    }

    // ---- reset shared state for next graph replay (last-done CTA) ----
    __syncthreads();
    __shared__ int s_last;
    if (t == 0) {
        int d = atomicAdd(&g_done, 1);
        s_last = (d == NCTAS - 1);
    }
    __syncthreads();
    if (s_last && t < NUM_BINS) {
        g_hist[0][t] = 0;
        g_hist[1][t] = 0;
        g_hist[2][t] = 0;
        if (t == 0) { g_ticket = 0; g_done = 0; }
    }
}

extern "C" void kernel_launch(void* const* d_in, const int* in_sizes, int n_in,
                              void* d_out, int out_size) {
    const float* img = (const float*)d_in[0];
    float* out = (float*)d_out;
    const int npx = in_sizes[0] / NCH_TOTAL;   // 2048*4096

    cudaFuncSetAttribute(equalize_fused_kernel,
                         cudaFuncAttributeMaxDynamicSharedMemorySize,
                         BIN_SMEM);
    equalize_fused_kernel<<<NCTAS, TPB, BIN_SMEM>>>(img, out, npx);
}

// round 14
// speedup vs baseline: 1.0443x; 1.0443x over previous
#include <cuda_runtime.h>
#include <stdint.h>

#define NUM_BINS 256
#define NCH_SAMPLE 3
#define NCH_TOTAL 6
#define NPX (2048 * 4096)

#define SLICES 197                 // slices per channel
#define NCTAS (SLICES * 3)         // 591 CTAs total (<= 148 SMs * 4 resident)
#define GPC 10646                  // float4 groups per CTA: ceil(2097152/197)

// Static device scratch (zeroed at load; last-done CTA restores zeros each
// run, so graph replays are deterministic).
__device__ int g_hist[NCH_SAMPLE][NUM_BINS];
__device__ int g_ticket;
__device__ int g_done;

// Single persistent kernel. Phases A (hist+binize, smem-atomic heavy) and
// B (target copy, pure bandwidth) are INTERLEAVED per iteration so the
// atomic pipe and DRAM pipe overlap within every warp, chip-wide.
//  C: spin on ticket, build own channel's LUT
//  D: apply LUT from smem bins -> output
__global__ void __launch_bounds__(256, 4)
equalize_fused_kernel(const float* __restrict__ img,
                      float* __restrict__ out, int npx) {
    const int t = threadIdx.x;
    const int c  = blockIdx.x % NCH_SAMPLE;     // channel
    const int sl = blockIdx.x / NCH_SAMPLE;     // slice within channel
    const int n4 = npx >> 2;
    const int base = sl * GPC;
    const int end  = min(base + GPC, n4);

    __shared__ uint32_t s_bins[GPC];            // 42584 B packed bins
    __shared__ int      s_hist[4][NUM_BINS];    // 4 KB replicas / scan scratch
    __shared__ float    s_lut[NUM_BINS];        // 1 KB
    __shared__ int      s_lastnz;

    for (int i = t; i < 4 * NUM_BINS; i += blockDim.x) ((int*)s_hist)[i] = 0;
    __syncthreads();

    // ---- Phases A+B interleaved ----
    {
        const float4* p  = (const float4*)(img + (size_t)c * npx);
        const float4* cp = (const float4*)(img + (size_t)NCH_SAMPLE * npx);
        float4*       cq = (float4*)(out + (size_t)NCH_SAMPLE * npx);
        const int tn4 = NCH_SAMPLE * n4;
        const int cstride = NCTAS * 256;
        const int sub = t & 3;

        int gi = base + t;                      // sample cursor (per-slice)
        int ci = blockIdx.x * 256 + t;          // copy cursor (grid-stride)

        while (gi < end || ci < tn4) {
            const bool gs = gi < end;
            const bool cs = ci < tn4;
            float4 v, a;
            if (gs) v = __ldcs(&p[gi]);         // both loads in flight before
            if (cs) a = __ldcs(&cp[ci]);        // any dependent work
            if (cs) __stcs(&cq[ci], a);
            if (gs) {
                int b0 = min(255, max(0, (int)v.x));
                int b1 = min(255, max(0, (int)v.y));
                int b2 = min(255, max(0, (int)v.z));
                int b3 = min(255, max(0, (int)v.w));
                s_bins[gi - base] = (uint32_t)b0 | ((uint32_t)b1 << 8) |
                                    ((uint32_t)b2 << 16) | ((uint32_t)b3 << 24);
                atomicAdd(&s_hist[sub][b0], 1);
                atomicAdd(&s_hist[sub][b1], 1);
                atomicAdd(&s_hist[sub][b2], 1);
                atomicAdd(&s_hist[sub][b3], 1);
            }
            gi += 256;
            ci += cstride;
        }
    }
    __syncthreads();
    {
        int s = s_hist[0][t] + s_hist[1][t] + s_hist[2][t] + s_hist[3][t];
        if (s) atomicAdd(&g_hist[c][t], s);
    }
    __threadfence();                            // release hist before arrive
    if (t == 0) atomicAdd(&g_ticket, 1);

    // ---- Phase C: wait for all hist arrivals, then build this channel's LUT
    if (t == 0) {
        while (*(volatile int*)&g_ticket != NCTAS) __nanosleep(128);
    }
    __syncthreads();
    __threadfence();

    {
        int* hist = s_hist[0];
        int* cum  = s_hist[1];
        int h = __ldcg(&g_hist[c][t]);
        hist[t] = h;
        cum[t]  = h;
        if (t == 0) s_lastnz = 0;
        __syncthreads();

        #pragma unroll
        for (int off = 1; off < NUM_BINS; off <<= 1) {
            int tmp = (t >= off) ? cum[t - off] : 0;
            __syncthreads();
            cum[t] += tmp;
            __syncthreads();
        }
        if (h > 0) atomicMax(&s_lastnz, t);
        __syncthreads();

        const int total = cum[NUM_BINS - 1];
        const int step  = (total - hist[s_lastnz]) / (NUM_BINS - 1);

        float outv;
        if (step == 0) {
            outv = (float)t;                    // identity when step==0
        } else {
            int l = (t == 0) ? 0 : (cum[t - 1] + (step >> 1)) / step;
            outv = (float)min(NUM_BINS - 1, max(0, l));
        }
        s_lut[t] = outv;
        __syncthreads();
    }

    // ---- Phase D: apply from smem bins (no global re-read of samples) ----
    {
        float4* q = (float4*)(out + (size_t)c * npx);
        for (int g = base + t; g < end; g += 256) {
            uint32_t w = s_bins[g - base];
            float4 r;
            r.x = s_lut[w & 255];
            r.y = s_lut[(w >> 8) & 255];
            r.z = s_lut[(w >> 16) & 255];
            r.w = s_lut[w >> 24];
            __stcs(&q[g], r);
        }
    }

    // ---- reset shared state for next graph replay (last-done CTA) ----
    __syncthreads();
    __shared__ int s_last;
    if (t == 0) {
        int d = atomicAdd(&g_done, 1);
        s_last = (d == NCTAS - 1);
    }
    __syncthreads();
    if (s_last) {
        g_hist[0][t] = 0;
        g_hist[1][t] = 0;
        g_hist[2][t] = 0;
        if (t == 0) { g_ticket = 0; g_done = 0; }
    }
}

extern "C" void kernel_launch(void* const* d_in, const int* in_sizes, int n_in,
                              void* d_out, int out_size) {
    const float* img = (const float*)d_in[0];
    float* out = (float*)d_out;
    const int npx = in_sizes[0] / NCH_TOTAL;   // 2048*4096

    equalize_fused_kernel<<<NCTAS, 256>>>(img, out, npx);
}